// round 3
// baseline (speedup 1.0000x reference)
#include <cuda_runtime.h>

#define BB   8
#define SS   1024
#define HID  1024
#define NH   16
#define HD   64

// Scratch for Q,K,V in [b,h,s,d] layout (32 MB each). Static __device__ arrays
// per the allocation-free rule.
__device__ float g_Q[BB * NH * SS * HD];
__device__ float g_K[BB * NH * SS * HD];
__device__ float g_V[BB * NH * SS * HD];

// ---------------------------------------------------------------------------
// Kernel 1: QKV projection GEMM.
//   C[M=8192, N=1024] = X[M,K=1024] * W[N,K]^T + bias, for W in {Wq,Wk,Wv}
//   (blockIdx.z selects the matrix). Q additionally scaled by 1/sqrt(64).
//   Output written directly into [b,h,s,d] scratch layout.
// 128x128 block tile, BK=16, 256 threads, 8x8 per-thread microtile.
// ---------------------------------------------------------------------------
__global__ __launch_bounds__(256) void qkv_gemm_kernel(
    const float* __restrict__ X,
    const float* __restrict__ Wq, const float* __restrict__ bq,
    const float* __restrict__ Wk, const float* __restrict__ bk,
    const float* __restrict__ Wv, const float* __restrict__ bv)
{
    __shared__ float As[16][128];
    __shared__ float Bs[16][128];

    const int z = blockIdx.z;
    const float* __restrict__ W    = (z == 0) ? Wq : (z == 1) ? Wk : Wv;
    const float* __restrict__ bias = (z == 0) ? bq : (z == 1) ? bk : bv;
    float* __restrict__ dst        = (z == 0) ? g_Q : (z == 1) ? g_K : g_V;
    const float scale = (z == 0) ? 0.125f : 1.0f;  // 1/sqrt(HD) folded into Q

    const int tid = threadIdx.x;
    const int lr  = tid >> 1;          // 0..127 : tile row being loaded
    const int lk  = (tid & 1) * 8;     // 0 or 8 : k-offset being loaded
    const int m0  = blockIdx.x * 128;
    const int n0  = blockIdx.y * 128;
    const int ty  = tid >> 4;          // 0..15
    const int tx  = tid & 15;          // 0..15

    const float* Ag = X + (size_t)(m0 + lr) * HID + lk;
    const float* Bg = W + (size_t)(n0 + lr) * HID + lk;

    float acc[8][8];
    #pragma unroll
    for (int i = 0; i < 8; i++)
        #pragma unroll
        for (int j = 0; j < 8; j++) acc[i][j] = 0.0f;

    for (int k0 = 0; k0 < HID; k0 += 16) {
        float4 a0 = *(const float4*)(Ag + k0);
        float4 a1 = *(const float4*)(Ag + k0 + 4);
        float4 b0 = *(const float4*)(Bg + k0);
        float4 b1 = *(const float4*)(Bg + k0 + 4);
        __syncthreads();   // previous iteration's readers done before overwrite
        As[lk + 0][lr] = a0.x; As[lk + 1][lr] = a0.y;
        As[lk + 2][lr] = a0.z; As[lk + 3][lr] = a0.w;
        As[lk + 4][lr] = a1.x; As[lk + 5][lr] = a1.y;
        As[lk + 6][lr] = a1.z; As[lk + 7][lr] = a1.w;
        Bs[lk + 0][lr] = b0.x; Bs[lk + 1][lr] = b0.y;
        Bs[lk + 2][lr] = b0.z; Bs[lk + 3][lr] = b0.w;
        Bs[lk + 4][lr] = b1.x; Bs[lk + 5][lr] = b1.y;
        Bs[lk + 6][lr] = b1.z; Bs[lk + 7][lr] = b1.w;
        __syncthreads();

        #pragma unroll
        for (int kk = 0; kk < 16; kk++) {
            float a[8], b[8];
            *(float4*)&a[0] = *(const float4*)&As[kk][ty * 8];
            *(float4*)&a[4] = *(const float4*)&As[kk][ty * 8 + 4];
            *(float4*)&b[0] = *(const float4*)&Bs[kk][tx * 8];
            *(float4*)&b[4] = *(const float4*)&Bs[kk][tx * 8 + 4];
            #pragma unroll
            for (int i = 0; i < 8; i++)
                #pragma unroll
                for (int j = 0; j < 8; j++)
                    acc[i][j] += a[i] * b[j];
        }
    }

    // Epilogue: bias + scale, scatter into [b,h,s,d].
    // n-range of this thread: 8 contiguous values, 8-aligned, within ONE head
    // (head width 64, 8 | 64)  ->  d is contiguous -> two float4 stores.
    const int n_base = n0 + tx * 8;
    const int h      = n_base >> 6;
    const int d_base = n_base & 63;
    float bb[8];
    #pragma unroll
    for (int j = 0; j < 8; j++) bb[j] = bias[n_base + j];

    #pragma unroll
    for (int i = 0; i < 8; i++) {
        int m    = m0 + ty * 8 + i;
        int bidx = m >> 10;       // batch
        int srow = m & 1023;      // seq position
        float* drow = dst + (((size_t)(bidx * NH + h)) * SS + srow) * HD + d_base;
        float4 v0, v1;
        v0.x = (acc[i][0] + bb[0]) * scale;
        v0.y = (acc[i][1] + bb[1]) * scale;
        v0.z = (acc[i][2] + bb[2]) * scale;
        v0.w = (acc[i][3] + bb[3]) * scale;
        v1.x = (acc[i][4] + bb[4]) * scale;
        v1.y = (acc[i][5] + bb[5]) * scale;
        v1.z = (acc[i][6] + bb[6]) * scale;
        v1.w = (acc[i][7] + bb[7]) * scale;
        *(float4*)(drow)     = v0;
        *(float4*)(drow + 4) = v1;
    }
}

// ---------------------------------------------------------------------------
// Kernel 2: flash attention (online softmax), fp32.
// Grid: (S/128, B*NH). 128 threads/block; each thread owns ONE q-row:
//   q[64] and o[64] in registers; K/V tiles of 64 rows in smem; all smem
//   reads in the dot/PV loops are warp-uniform -> broadcast, conflict-free.
// Online softmax processed in chunks of 8 columns (register arrays stay
// fully unrolled; rescale overhead 64/(8*128) ~ 6%).
// ---------------------------------------------------------------------------
__global__ __launch_bounds__(128) void flash_kernel(
    const float* __restrict__ mask, float* __restrict__ out)
{
    __shared__ float Ks[64][64];
    __shared__ float Vs[64][64];
    __shared__ float Ms[64];

    const int tid  = threadIdx.x;
    const int bh   = blockIdx.y;       // 0..127
    const int b    = bh >> 4;
    const int h    = bh & 15;
    const int qrow = blockIdx.x * 128 + tid;

    const float* __restrict__ qp = g_Q + ((size_t)bh * SS + qrow) * HD;
    const float* __restrict__ kb = g_K + (size_t)bh * SS * HD;
    const float* __restrict__ vb = g_V + (size_t)bh * SS * HD;
    const float* __restrict__ mp = mask + (size_t)b * SS;

    float q[64];
    #pragma unroll
    for (int i = 0; i < 16; i++) {
        float4 t = ((const float4*)qp)[i];
        q[4*i + 0] = t.x; q[4*i + 1] = t.y;
        q[4*i + 2] = t.z; q[4*i + 3] = t.w;
    }

    float o[64];
    #pragma unroll
    for (int d = 0; d < 64; d++) o[d] = 0.0f;
    float mrun = -1e30f, lrun = 0.0f;

    for (int kt = 0; kt < SS; kt += 64) {
        __syncthreads();   // previous tile fully consumed
        #pragma unroll
        for (int i = 0; i < 8; i++) {
            int idx = i * 512 + tid * 4;   // coalesced global, conflict-free smem
            *(float4*)&Ks[0][idx] = *(const float4*)(kb + (size_t)kt * HD + idx);
            *(float4*)&Vs[0][idx] = *(const float4*)(vb + (size_t)kt * HD + idx);
        }
        if (tid < 64) Ms[tid] = mp[kt + tid];
        __syncthreads();

        for (int jc = 0; jc < 64; jc += 8) {
            float s[8];
            #pragma unroll
            for (int jj = 0; jj < 8; jj++) {
                const float4* kr = (const float4*)Ks[jc + jj];
                float a0 = 0.f, a1 = 0.f, a2 = 0.f, a3 = 0.f;  // 4 chains for ILP
                #pragma unroll
                for (int d4 = 0; d4 < 16; d4 += 4) {
                    float4 k0 = kr[d4 + 0], k1 = kr[d4 + 1];
                    float4 k2 = kr[d4 + 2], k3 = kr[d4 + 3];
                    a0 += q[4*d4 +  0]*k0.x + q[4*d4 +  1]*k0.y
                        + q[4*d4 +  2]*k0.z + q[4*d4 +  3]*k0.w;
                    a1 += q[4*d4 +  4]*k1.x + q[4*d4 +  5]*k1.y
                        + q[4*d4 +  6]*k1.z + q[4*d4 +  7]*k1.w;
                    a2 += q[4*d4 +  8]*k2.x + q[4*d4 +  9]*k2.y
                        + q[4*d4 + 10]*k2.z + q[4*d4 + 11]*k2.w;
                    a3 += q[4*d4 + 12]*k3.x + q[4*d4 + 13]*k3.y
                        + q[4*d4 + 14]*k3.z + q[4*d4 + 15]*k3.w;
                }
                s[jj] = (a0 + a1) + (a2 + a3) + Ms[jc + jj];
            }

            float cmax = s[0];
            #pragma unroll
            for (int jj = 1; jj < 8; jj++) cmax = fmaxf(cmax, s[jj]);
            float mnew = fmaxf(mrun, cmax);
            float corr = __expf(mrun - mnew);   // exp(-1e30) == 0, safe first tile
            mrun = mnew;
            lrun *= corr;
            #pragma unroll
            for (int d = 0; d < 64; d++) o[d] *= corr;

            #pragma unroll
            for (int jj = 0; jj < 8; jj++) {
                float p = __expf(s[jj] - mnew);
                lrun += p;
                const float4* vr = (const float4*)Vs[jc + jj];
                #pragma unroll
                for (int d4 = 0; d4 < 16; d4++) {
                    float4 vv = vr[d4];
                    o[4*d4 + 0] += p * vv.x;
                    o[4*d4 + 1] += p * vv.y;
                    o[4*d4 + 2] += p * vv.z;
                    o[4*d4 + 3] += p * vv.w;
                }
            }
        }
    }

    const float inv = 1.0f / lrun;
    float* op = out + ((size_t)b * SS + qrow) * HID + h * HD;
    #pragma unroll
    for (int i = 0; i < 16; i++) {
        float4 t;
        t.x = o[4*i + 0] * inv; t.y = o[4*i + 1] * inv;
        t.z = o[4*i + 2] * inv; t.w = o[4*i + 3] * inv;
        ((float4*)op)[i] = t;
    }
}

// ---------------------------------------------------------------------------
extern "C" void kernel_launch(void* const* d_in, const int* in_sizes, int n_in,
                              void* d_out, int out_size)
{
    const float* X    = (const float*)d_in[0];
    const float* mask = (const float*)d_in[1];
    const float* Wq   = (const float*)d_in[2];
    const float* bq   = (const float*)d_in[3];
    const float* Wk   = (const float*)d_in[4];
    const float* bk   = (const float*)d_in[5];
    const float* Wv   = (const float*)d_in[6];
    const float* bv   = (const float*)d_in[7];
    float* out = (float*)d_out;

    dim3 g1(64, 8, 3);                 // M/128, N/128, {Q,K,V}
    qkv_gemm_kernel<<<g1, 256>>>(X, Wq, bq, Wk, bk, Wv, bv);

    dim3 g2(8, 128);                   // S/128, B*NH
    flash_kernel<<<g2, 128>>>(mask, out);
}

// round 7
// speedup vs baseline: 1.3919x; 1.3919x over previous
#include <cuda_runtime.h>
#include <cuda_bf16.h>
#include <cstdint>

#define BB   8
#define SS   1024
#define HID  1024
#define NH   16
#define HD   64

// ---------------------------------------------------------------------------
// Device scratch (allocation-free rule): Q/K/V fp32 in [b,h,s,d], plus
// bf16 hi/lo splits of X and the three weight matrices.
// ---------------------------------------------------------------------------
__device__ float g_Q[BB * NH * SS * HD];
__device__ float g_K[BB * NH * SS * HD];
__device__ float g_V[BB * NH * SS * HD];
__device__ __nv_bfloat16 g_Xh[BB * SS * HID];
__device__ __nv_bfloat16 g_Xl[BB * SS * HID];
__device__ __nv_bfloat16 g_Wh[3 * HID * HID];
__device__ __nv_bfloat16 g_Wl[3 * HID * HID];

// ---------------------------------------------------------------------------
// PTX helpers available on plain sm_100 target (sm_80+ features only).
// ---------------------------------------------------------------------------
__device__ __forceinline__ uint32_t smem_u32(const void* p) {
    uint32_t a;
    asm("{ .reg .u64 t; cvta.to.shared.u64 t, %1; cvt.u32.u64 %0, t; }"
        : "=r"(a) : "l"(p));
    return a;
}
__device__ __forceinline__ void cp16(uint32_t s, const void* g) {
    asm volatile("cp.async.cg.shared.global [%0], [%1], 16;" :: "r"(s), "l"(g));
}
#define CP_COMMIT() asm volatile("cp.async.commit_group;" ::: "memory")
#define CP_WAIT(n)  asm volatile("cp.async.wait_group %0;" :: "n"(n) : "memory")

__device__ __forceinline__ void ldsm_x4(uint32_t* r, uint32_t a) {
    asm volatile("ldmatrix.sync.aligned.m8n8.x4.shared.b16 {%0,%1,%2,%3}, [%4];"
                 : "=r"(r[0]), "=r"(r[1]), "=r"(r[2]), "=r"(r[3]) : "r"(a));
}
// NON-trans x2: for B stored [n][k] (k contiguous) this directly yields the
// mma row.col B fragment (thread t: n = t/4, k = 2*(t%4)+j).
__device__ __forceinline__ void ldsm_x2(uint32_t* r, uint32_t a) {
    asm volatile("ldmatrix.sync.aligned.m8n8.x2.shared.b16 {%0,%1}, [%2];"
                 : "=r"(r[0]), "=r"(r[1]) : "r"(a));
}
__device__ __forceinline__ void mma_bf16(float* d, const uint32_t* a,
                                         const uint32_t* b) {
    asm volatile("mma.sync.aligned.m16n8k16.row.col.f32.bf16.bf16.f32 "
                 "{%0,%1,%2,%3}, {%4,%5,%6,%7}, {%8,%9}, {%0,%1,%2,%3};"
                 : "+f"(d[0]), "+f"(d[1]), "+f"(d[2]), "+f"(d[3])
                 : "r"(a[0]), "r"(a[1]), "r"(a[2]), "r"(a[3]),
                   "r"(b[0]), "r"(b[1]));
}

// ---------------------------------------------------------------------------
// Convert fp32 -> bf16 hi + bf16 lo (residual).  which: 0 = X, 1 = W[z]
// ---------------------------------------------------------------------------
__global__ __launch_bounds__(256) void cvt_kernel(const float* __restrict__ src,
                                                  int which, int z, int n)
{
    int i = (blockIdx.x * 256 + threadIdx.x) * 4;
    if (i >= n) return;
    __nv_bfloat16* hi = (which == 0) ? g_Xh : (g_Wh + (size_t)z * HID * HID);
    __nv_bfloat16* lo = (which == 0) ? g_Xl : (g_Wl + (size_t)z * HID * HID);
    float4 v = *(const float4*)(src + i);
    __nv_bfloat16 h0 = __float2bfloat16(v.x), h1 = __float2bfloat16(v.y);
    __nv_bfloat16 h2 = __float2bfloat16(v.z), h3 = __float2bfloat16(v.w);
    __nv_bfloat16 l0 = __float2bfloat16(v.x - __bfloat162float(h0));
    __nv_bfloat16 l1 = __float2bfloat16(v.y - __bfloat162float(h1));
    __nv_bfloat16 l2 = __float2bfloat16(v.z - __bfloat162float(h2));
    __nv_bfloat16 l3 = __float2bfloat16(v.w - __bfloat162float(h3));
    ((__nv_bfloat162*)(hi + i))[0] = __nv_bfloat162(h0, h1);
    ((__nv_bfloat162*)(hi + i))[1] = __nv_bfloat162(h2, h3);
    ((__nv_bfloat162*)(lo + i))[0] = __nv_bfloat162(l0, l1);
    ((__nv_bfloat162*)(lo + i))[1] = __nv_bfloat162(l2, l3);
}

// ---------------------------------------------------------------------------
// mma.sync QKV GEMM: C[8192,1024] = X·W^T + bias, z selects {Q,K,V}.
// 128x128 CTA tile, 8 warps (2x4), warp tile 64x32, BK=32, cp.async
// double-buffered, hi/lo bf16 split (3 mma products per tile).
// SMEM per stage: 4 matrices x 128 rows x stride 40 bf16 = 40960 B.
// ---------------------------------------------------------------------------
#define STRIDE   40                       // bf16 elements per smem row (pad 8)
#define MAT_SZ   (128 * STRIDE * 2)       // 10240 bytes
#define STAGE_SZ (4 * MAT_SZ)             // 40960 bytes
#define SMEM_GEMM (2 * STAGE_SZ)          // 81920 bytes
#define NSTAGES  (HID / 32)               // 32

__global__ __launch_bounds__(256) void qkv_gemm_mma(
    const float* __restrict__ bq, const float* __restrict__ bk,
    const float* __restrict__ bv)
{
    extern __shared__ char smem[];
    const uint32_t sb = smem_u32(smem);
    const int tid  = threadIdx.x;
    const int wid  = tid >> 5;
    const int lane = tid & 31;
    const int wm   = wid >> 2;            // 0..1  (m offset /64)
    const int wn   = wid & 3;             // 0..3  (n offset /32)

    const int z  = blockIdx.z;
    const int m0 = blockIdx.x * 128;
    const int n0 = blockIdx.y * 128;
    const float* __restrict__ bias = (z == 0) ? bq : (z == 1) ? bk : bv;
    float* __restrict__ dst        = (z == 0) ? g_Q : (z == 1) ? g_K : g_V;
    const float scale = (z == 0) ? 0.125f : 1.0f;
    const __nv_bfloat16* __restrict__ gA_h = g_Xh + (size_t)m0 * HID;
    const __nv_bfloat16* __restrict__ gA_l = g_Xl + (size_t)m0 * HID;
    const __nv_bfloat16* __restrict__ gB_h = g_Wh + (size_t)z * HID * HID + (size_t)n0 * HID;
    const __nv_bfloat16* __restrict__ gB_l = g_Wl + (size_t)z * HID * HID + (size_t)n0 * HID;

    float acc[4][4][4];
    #pragma unroll
    for (int mi = 0; mi < 4; mi++)
        #pragma unroll
        for (int ni = 0; ni < 4; ni++)
            #pragma unroll
            for (int e = 0; e < 4; e++) acc[mi][ni][e] = 0.0f;

    // per-lane ldmatrix address components
    const int aRow = lane & 15;             // row within 16-row tile
    const int aCol = (lane >> 4) * 8;       // k half
    const int bRow = lane & 7;              // n row within 8
    const int bCol = ((lane >> 3) & 1) * 8; // k half (lanes 0-15 used)

    // stage loader: 512 16B-chunks per matrix, 2 per thread per matrix
    auto load_stage = [&](int c, int st) {
        const __nv_bfloat16* gb[4] = { gA_h + c * 32, gA_l + c * 32,
                                       gB_h + c * 32, gB_l + c * 32 };
        const uint32_t sbase = sb + st * STAGE_SZ;
        #pragma unroll
        for (int j = 0; j < 2; j++) {
            const int t   = tid + j * 256;
            const int row = t >> 2;
            const int cb  = t & 3;
            const uint32_t soff = (uint32_t)(row * STRIDE + cb * 8) * 2;
            const size_t  goff  = (size_t)row * HID + cb * 8;
            #pragma unroll
            for (int mt = 0; mt < 4; mt++)
                cp16(sbase + mt * MAT_SZ + soff, gb[mt] + goff);
        }
    };

    load_stage(0, 0);
    CP_COMMIT();

    for (int c = 0; c < NSTAGES; c++) {
        const int st = c & 1;
        if (c + 1 < NSTAGES) {
            load_stage(c + 1, st ^ 1);
            CP_COMMIT();
            CP_WAIT(1);
        } else {
            CP_WAIT(0);
        }
        __syncthreads();

        const uint32_t sbase = sb + st * STAGE_SZ;
        #pragma unroll
        for (int ks = 0; ks < 2; ks++) {
            uint32_t ah[4][4], al[4][4], bh[4][2], bl[4][2];
            #pragma unroll
            for (int mi = 0; mi < 4; mi++) {
                const uint32_t ro = (uint32_t)((wm * 64 + mi * 16 + aRow) * STRIDE
                                               + ks * 16 + aCol) * 2;
                ldsm_x4(ah[mi], sbase + 0 * MAT_SZ + ro);
                ldsm_x4(al[mi], sbase + 1 * MAT_SZ + ro);
            }
            #pragma unroll
            for (int ni = 0; ni < 4; ni++) {
                const uint32_t ro = (uint32_t)((wn * 32 + ni * 8 + bRow) * STRIDE
                                               + ks * 16 + bCol) * 2;
                ldsm_x2(bh[ni], sbase + 2 * MAT_SZ + ro);
                ldsm_x2(bl[ni], sbase + 3 * MAT_SZ + ro);
            }
            #pragma unroll
            for (int mi = 0; mi < 4; mi++)
                #pragma unroll
                for (int ni = 0; ni < 4; ni++) {
                    mma_bf16(acc[mi][ni], ah[mi], bh[ni]);
                    mma_bf16(acc[mi][ni], ah[mi], bl[ni]);
                    mma_bf16(acc[mi][ni], al[mi], bh[ni]);
                }
        }
        __syncthreads();
    }

    // Epilogue: d0,d1 -> (row, col+0/1); d2,d3 -> (row+8, col+0/1)
    const int r0 = lane >> 2;
    const int cp = (lane & 3) * 2;
    #pragma unroll
    for (int mi = 0; mi < 4; mi++) {
        #pragma unroll
        for (int ni = 0; ni < 4; ni++) {
            const int n  = n0 + wn * 32 + ni * 8 + cp;
            const int h  = n >> 6;
            const int d  = n & 63;
            const float b0 = bias[n], b1 = bias[n + 1];
            #pragma unroll
            for (int half = 0; half < 2; half++) {
                const int m    = m0 + wm * 64 + mi * 16 + r0 + half * 8;
                const int bidx = m >> 10;
                const int srow = m & 1023;
                float2 v;
                v.x = (acc[mi][ni][half * 2 + 0] + b0) * scale;
                v.y = (acc[mi][ni][half * 2 + 1] + b1) * scale;
                *(float2*)(dst + (((size_t)(bidx * NH + h)) * SS + srow) * HD + d) = v;
            }
        }
    }
}

// ---------------------------------------------------------------------------
// Kernel 2: flash attention (online softmax), fp32 — unchanged (proven).
// ---------------------------------------------------------------------------
__global__ __launch_bounds__(128) void flash_kernel(
    const float* __restrict__ mask, float* __restrict__ out)
{
    __shared__ float Ks[64][64];
    __shared__ float Vs[64][64];
    __shared__ float Ms[64];

    const int tid  = threadIdx.x;
    const int bh   = blockIdx.y;
    const int b    = bh >> 4;
    const int h    = bh & 15;
    const int qrow = blockIdx.x * 128 + tid;

    const float* __restrict__ qp = g_Q + ((size_t)bh * SS + qrow) * HD;
    const float* __restrict__ kb = g_K + (size_t)bh * SS * HD;
    const float* __restrict__ vb = g_V + (size_t)bh * SS * HD;
    const float* __restrict__ mp = mask + (size_t)b * SS;

    float q[64];
    #pragma unroll
    for (int i = 0; i < 16; i++) {
        float4 t = ((const float4*)qp)[i];
        q[4*i + 0] = t.x; q[4*i + 1] = t.y;
        q[4*i + 2] = t.z; q[4*i + 3] = t.w;
    }

    float o[64];
    #pragma unroll
    for (int d = 0; d < 64; d++) o[d] = 0.0f;
    float mrun = -1e30f, lrun = 0.0f;

    for (int kt = 0; kt < SS; kt += 64) {
        __syncthreads();
        #pragma unroll
        for (int i = 0; i < 8; i++) {
            int idx = i * 512 + tid * 4;
            *(float4*)&Ks[0][idx] = *(const float4*)(kb + (size_t)kt * HD + idx);
            *(float4*)&Vs[0][idx] = *(const float4*)(vb + (size_t)kt * HD + idx);
        }
        if (tid < 64) Ms[tid] = mp[kt + tid];
        __syncthreads();

        for (int jc = 0; jc < 64; jc += 8) {
            float s[8];
            #pragma unroll
            for (int jj = 0; jj < 8; jj++) {
                const float4* kr = (const float4*)Ks[jc + jj];
                float a0 = 0.f, a1 = 0.f, a2 = 0.f, a3 = 0.f;
                #pragma unroll
                for (int d4 = 0; d4 < 16; d4 += 4) {
                    float4 k0 = kr[d4 + 0], k1 = kr[d4 + 1];
                    float4 k2 = kr[d4 + 2], k3 = kr[d4 + 3];
                    a0 += q[4*d4 +  0]*k0.x + q[4*d4 +  1]*k0.y
                        + q[4*d4 +  2]*k0.z + q[4*d4 +  3]*k0.w;
                    a1 += q[4*d4 +  4]*k1.x + q[4*d4 +  5]*k1.y
                        + q[4*d4 +  6]*k1.z + q[4*d4 +  7]*k1.w;
                    a2 += q[4*d4 +  8]*k2.x + q[4*d4 +  9]*k2.y
                        + q[4*d4 + 10]*k2.z + q[4*d4 + 11]*k2.w;
                    a3 += q[4*d4 + 12]*k3.x + q[4*d4 + 13]*k3.y
                        + q[4*d4 + 14]*k3.z + q[4*d4 + 15]*k3.w;
                }
                s[jj] = (a0 + a1) + (a2 + a3) + Ms[jc + jj];
            }

            float cmax = s[0];
            #pragma unroll
            for (int jj = 1; jj < 8; jj++) cmax = fmaxf(cmax, s[jj]);
            float mnew = fmaxf(mrun, cmax);
            float corr = __expf(mrun - mnew);
            mrun = mnew;
            lrun *= corr;
            #pragma unroll
            for (int d = 0; d < 64; d++) o[d] *= corr;

            #pragma unroll
            for (int jj = 0; jj < 8; jj++) {
                float p = __expf(s[jj] - mnew);
                lrun += p;
                const float4* vr = (const float4*)Vs[jc + jj];
                #pragma unroll
                for (int d4 = 0; d4 < 16; d4++) {
                    float4 vv = vr[d4];
                    o[4*d4 + 0] += p * vv.x;
                    o[4*d4 + 1] += p * vv.y;
                    o[4*d4 + 2] += p * vv.z;
                    o[4*d4 + 3] += p * vv.w;
                }
            }
        }
    }

    const float inv = 1.0f / lrun;
    float* op = out + ((size_t)b * SS + qrow) * HID + h * HD;
    #pragma unroll
    for (int i = 0; i < 16; i++) {
        float4 t;
        t.x = o[4*i + 0] * inv; t.y = o[4*i + 1] * inv;
        t.z = o[4*i + 2] * inv; t.w = o[4*i + 3] * inv;
        ((float4*)op)[i] = t;
    }
}

// ---------------------------------------------------------------------------
extern "C" void kernel_launch(void* const* d_in, const int* in_sizes, int n_in,
                              void* d_out, int out_size)
{
    const float* X    = (const float*)d_in[0];
    const float* mask = (const float*)d_in[1];
    const float* Wq   = (const float*)d_in[2];
    const float* bq   = (const float*)d_in[3];
    const float* Wk   = (const float*)d_in[4];
    const float* bk   = (const float*)d_in[5];
    const float* Wv   = (const float*)d_in[6];
    const float* bv   = (const float*)d_in[7];
    float* out = (float*)d_out;

    cudaFuncSetAttribute(qkv_gemm_mma,
                         cudaFuncAttributeMaxDynamicSharedMemorySize, SMEM_GEMM);

    cvt_kernel<<<8192, 256>>>(X,  0, 0, BB * SS * HID);
    cvt_kernel<<<1024, 256>>>(Wq, 1, 0, HID * HID);
    cvt_kernel<<<1024, 256>>>(Wk, 1, 1, HID * HID);
    cvt_kernel<<<1024, 256>>>(Wv, 1, 2, HID * HID);

    dim3 g1(64, 8, 3);                 // M/128, N/128, {Q,K,V}
    qkv_gemm_mma<<<g1, 256, SMEM_GEMM>>>(bq, bk, bv);

    dim3 g2(8, 128);                   // S/128, B*NH
    flash_kernel<<<g2, 128>>>(mask, out);
}

// round 8
// speedup vs baseline: 1.4107x; 1.0135x over previous
#include <cuda_runtime.h>
#include <cuda_bf16.h>
#include <cstdint>

#define BB   8
#define SS   1024
#define HID  1024
#define NH   16
#define HD   64

// ---------------------------------------------------------------------------
// Device scratch (allocation-free rule): Q/K/V fp32 in [b,h,s,d], plus
// bf16 hi/lo splits of X and the three weight matrices.
// ---------------------------------------------------------------------------
__device__ float g_Q[BB * NH * SS * HD];
__device__ float g_K[BB * NH * SS * HD];
__device__ float g_V[BB * NH * SS * HD];
__device__ __nv_bfloat16 g_Xh[BB * SS * HID];
__device__ __nv_bfloat16 g_Xl[BB * SS * HID];
__device__ __nv_bfloat16 g_Wh[3 * HID * HID];
__device__ __nv_bfloat16 g_Wl[3 * HID * HID];

// ---------------------------------------------------------------------------
// PTX helpers available on plain sm_100 target (sm_80+ features only).
// ---------------------------------------------------------------------------
__device__ __forceinline__ uint32_t smem_u32(const void* p) {
    uint32_t a;
    asm("{ .reg .u64 t; cvta.to.shared.u64 t, %1; cvt.u32.u64 %0, t; }"
        : "=r"(a) : "l"(p));
    return a;
}
__device__ __forceinline__ void cp16(uint32_t s, const void* g) {
    asm volatile("cp.async.cg.shared.global [%0], [%1], 16;" :: "r"(s), "l"(g));
}
#define CP_COMMIT() asm volatile("cp.async.commit_group;" ::: "memory")
#define CP_WAIT(n)  asm volatile("cp.async.wait_group %0;" :: "n"(n) : "memory")

__device__ __forceinline__ void ldsm_x4(uint32_t* r, uint32_t a) {
    asm volatile("ldmatrix.sync.aligned.m8n8.x4.shared.b16 {%0,%1,%2,%3}, [%4];"
                 : "=r"(r[0]), "=r"(r[1]), "=r"(r[2]), "=r"(r[3]) : "r"(a));
}
// NON-trans x2: for B stored [n][k] (k contiguous) this directly yields the
// mma row.col B fragment (thread t: n = t/4, k = 2*(t%4)+j).
__device__ __forceinline__ void ldsm_x2(uint32_t* r, uint32_t a) {
    asm volatile("ldmatrix.sync.aligned.m8n8.x2.shared.b16 {%0,%1}, [%2];"
                 : "=r"(r[0]), "=r"(r[1]) : "r"(a));
}
__device__ __forceinline__ void mma_bf16(float* d, const uint32_t* a,
                                         const uint32_t* b) {
    asm volatile("mma.sync.aligned.m16n8k16.row.col.f32.bf16.bf16.f32 "
                 "{%0,%1,%2,%3}, {%4,%5,%6,%7}, {%8,%9}, {%0,%1,%2,%3};"
                 : "+f"(d[0]), "+f"(d[1]), "+f"(d[2]), "+f"(d[3])
                 : "r"(a[0]), "r"(a[1]), "r"(a[2]), "r"(a[3]),
                   "r"(b[0]), "r"(b[1]));
}

// ---------------------------------------------------------------------------
// Convert fp32 -> bf16 hi + bf16 lo (residual).  which: 0 = X, 1 = W[z]
// ---------------------------------------------------------------------------
__global__ __launch_bounds__(256) void cvt_kernel(const float* __restrict__ src,
                                                  int which, int z, int n)
{
    int i = (blockIdx.x * 256 + threadIdx.x) * 4;
    if (i >= n) return;
    __nv_bfloat16* hi = (which == 0) ? g_Xh : (g_Wh + (size_t)z * HID * HID);
    __nv_bfloat16* lo = (which == 0) ? g_Xl : (g_Wl + (size_t)z * HID * HID);
    float4 v = *(const float4*)(src + i);
    __nv_bfloat16 h0 = __float2bfloat16(v.x), h1 = __float2bfloat16(v.y);
    __nv_bfloat16 h2 = __float2bfloat16(v.z), h3 = __float2bfloat16(v.w);
    __nv_bfloat16 l0 = __float2bfloat16(v.x - __bfloat162float(h0));
    __nv_bfloat16 l1 = __float2bfloat16(v.y - __bfloat162float(h1));
    __nv_bfloat16 l2 = __float2bfloat16(v.z - __bfloat162float(h2));
    __nv_bfloat16 l3 = __float2bfloat16(v.w - __bfloat162float(h3));
    ((__nv_bfloat162*)(hi + i))[0] = __nv_bfloat162(h0, h1);
    ((__nv_bfloat162*)(hi + i))[1] = __nv_bfloat162(h2, h3);
    ((__nv_bfloat162*)(lo + i))[0] = __nv_bfloat162(l0, l1);
    ((__nv_bfloat162*)(lo + i))[1] = __nv_bfloat162(l2, l3);
}

// ---------------------------------------------------------------------------
// mma.sync QKV GEMM: C[8192,1024] = X·W^T + bias, z selects {Q,K,V}.
// 128x128 CTA tile, 8 warps (2x4), warp tile 64x32, BK=32, cp.async
// double-buffered, hi/lo bf16 split (3 mma products per tile).
// SMEM per stage: 4 matrices x 128 rows x stride 40 bf16 = 40960 B.
// ---------------------------------------------------------------------------
#define STRIDE   40                       // bf16 elements per smem row (pad 8)
#define MAT_SZ   (128 * STRIDE * 2)       // 10240 bytes
#define STAGE_SZ (4 * MAT_SZ)             // 40960 bytes
#define SMEM_GEMM (2 * STAGE_SZ)          // 81920 bytes
#define NSTAGES  (HID / 32)               // 32

__global__ __launch_bounds__(256) void qkv_gemm_mma(
    const float* __restrict__ bq, const float* __restrict__ bk,
    const float* __restrict__ bv)
{
    extern __shared__ char smem[];
    const uint32_t sb = smem_u32(smem);
    const int tid  = threadIdx.x;
    const int wid  = tid >> 5;
    const int lane = tid & 31;
    const int wm   = wid >> 2;            // 0..1  (m offset /64)
    const int wn   = wid & 3;             // 0..3  (n offset /32)

    const int z  = blockIdx.z;
    const int m0 = blockIdx.x * 128;
    const int n0 = blockIdx.y * 128;
    const float* __restrict__ bias = (z == 0) ? bq : (z == 1) ? bk : bv;
    float* __restrict__ dst        = (z == 0) ? g_Q : (z == 1) ? g_K : g_V;
    const float scale = (z == 0) ? 0.125f : 1.0f;
    const __nv_bfloat16* __restrict__ gA_h = g_Xh + (size_t)m0 * HID;
    const __nv_bfloat16* __restrict__ gA_l = g_Xl + (size_t)m0 * HID;
    const __nv_bfloat16* __restrict__ gB_h = g_Wh + (size_t)z * HID * HID + (size_t)n0 * HID;
    const __nv_bfloat16* __restrict__ gB_l = g_Wl + (size_t)z * HID * HID + (size_t)n0 * HID;

    float acc[4][4][4];
    #pragma unroll
    for (int mi = 0; mi < 4; mi++)
        #pragma unroll
        for (int ni = 0; ni < 4; ni++)
            #pragma unroll
            for (int e = 0; e < 4; e++) acc[mi][ni][e] = 0.0f;

    // per-lane ldmatrix address components
    const int aRow = lane & 15;             // row within 16-row tile
    const int aCol = (lane >> 4) * 8;       // k half
    const int bRow = lane & 7;              // n row within 8
    const int bCol = ((lane >> 3) & 1) * 8; // k half (lanes 0-15 used)

    // stage loader: 512 16B-chunks per matrix, 2 per thread per matrix
    auto load_stage = [&](int c, int st) {
        const __nv_bfloat16* gb[4] = { gA_h + c * 32, gA_l + c * 32,
                                       gB_h + c * 32, gB_l + c * 32 };
        const uint32_t sbase = sb + st * STAGE_SZ;
        #pragma unroll
        for (int j = 0; j < 2; j++) {
            const int t   = tid + j * 256;
            const int row = t >> 2;
            const int cb  = t & 3;
            const uint32_t soff = (uint32_t)(row * STRIDE + cb * 8) * 2;
            const size_t  goff  = (size_t)row * HID + cb * 8;
            #pragma unroll
            for (int mt = 0; mt < 4; mt++)
                cp16(sbase + mt * MAT_SZ + soff, gb[mt] + goff);
        }
    };

    load_stage(0, 0);
    CP_COMMIT();

    for (int c = 0; c < NSTAGES; c++) {
        const int st = c & 1;
        if (c + 1 < NSTAGES) {
            load_stage(c + 1, st ^ 1);
            CP_COMMIT();
            CP_WAIT(1);
        } else {
            CP_WAIT(0);
        }
        __syncthreads();

        const uint32_t sbase = sb + st * STAGE_SZ;
        #pragma unroll
        for (int ks = 0; ks < 2; ks++) {
            uint32_t ah[4][4], al[4][4], bh[4][2], bl[4][2];
            #pragma unroll
            for (int mi = 0; mi < 4; mi++) {
                const uint32_t ro = (uint32_t)((wm * 64 + mi * 16 + aRow) * STRIDE
                                               + ks * 16 + aCol) * 2;
                ldsm_x4(ah[mi], sbase + 0 * MAT_SZ + ro);
                ldsm_x4(al[mi], sbase + 1 * MAT_SZ + ro);
            }
            #pragma unroll
            for (int ni = 0; ni < 4; ni++) {
                const uint32_t ro = (uint32_t)((wn * 32 + ni * 8 + bRow) * STRIDE
                                               + ks * 16 + bCol) * 2;
                ldsm_x2(bh[ni], sbase + 2 * MAT_SZ + ro);
                ldsm_x2(bl[ni], sbase + 3 * MAT_SZ + ro);
            }
            #pragma unroll
            for (int mi = 0; mi < 4; mi++)
                #pragma unroll
                for (int ni = 0; ni < 4; ni++) {
                    mma_bf16(acc[mi][ni], ah[mi], bh[ni]);
                    mma_bf16(acc[mi][ni], ah[mi], bl[ni]);
                    mma_bf16(acc[mi][ni], al[mi], bh[ni]);
                }
        }
        __syncthreads();
    }

    // Epilogue: d0,d1 -> (row, col+0/1); d2,d3 -> (row+8, col+0/1)
    const int r0 = lane >> 2;
    const int cp = (lane & 3) * 2;
    #pragma unroll
    for (int mi = 0; mi < 4; mi++) {
        #pragma unroll
        for (int ni = 0; ni < 4; ni++) {
            const int n  = n0 + wn * 32 + ni * 8 + cp;
            const int h  = n >> 6;
            const int d  = n & 63;
            const float b0 = bias[n], b1 = bias[n + 1];
            #pragma unroll
            for (int half = 0; half < 2; half++) {
                const int m    = m0 + wm * 64 + mi * 16 + r0 + half * 8;
                const int bidx = m >> 10;
                const int srow = m & 1023;
                float2 v;
                v.x = (acc[mi][ni][half * 2 + 0] + b0) * scale;
                v.y = (acc[mi][ni][half * 2 + 1] + b1) * scale;
                *(float2*)(dst + (((size_t)(bidx * NH + h)) * SS + srow) * HD + d) = v;
            }
        }
    }
}

// ---------------------------------------------------------------------------
// Kernel 2: flash attention (online softmax), fp32 — unchanged (proven).
// ---------------------------------------------------------------------------
__global__ __launch_bounds__(128) void flash_kernel(
    const float* __restrict__ mask, float* __restrict__ out)
{
    __shared__ float Ks[64][64];
    __shared__ float Vs[64][64];
    __shared__ float Ms[64];

    const int tid  = threadIdx.x;
    const int bh   = blockIdx.y;
    const int b    = bh >> 4;
    const int h    = bh & 15;
    const int qrow = blockIdx.x * 128 + tid;

    const float* __restrict__ qp = g_Q + ((size_t)bh * SS + qrow) * HD;
    const float* __restrict__ kb = g_K + (size_t)bh * SS * HD;
    const float* __restrict__ vb = g_V + (size_t)bh * SS * HD;
    const float* __restrict__ mp = mask + (size_t)b * SS;

    float q[64];
    #pragma unroll
    for (int i = 0; i < 16; i++) {
        float4 t = ((const float4*)qp)[i];
        q[4*i + 0] = t.x; q[4*i + 1] = t.y;
        q[4*i + 2] = t.z; q[4*i + 3] = t.w;
    }

    float o[64];
    #pragma unroll
    for (int d = 0; d < 64; d++) o[d] = 0.0f;
    float mrun = -1e30f, lrun = 0.0f;

    for (int kt = 0; kt < SS; kt += 64) {
        __syncthreads();
        #pragma unroll
        for (int i = 0; i < 8; i++) {
            int idx = i * 512 + tid * 4;
            *(float4*)&Ks[0][idx] = *(const float4*)(kb + (size_t)kt * HD + idx);
            *(float4*)&Vs[0][idx] = *(const float4*)(vb + (size_t)kt * HD + idx);
        }
        if (tid < 64) Ms[tid] = mp[kt + tid];
        __syncthreads();

        for (int jc = 0; jc < 64; jc += 8) {
            float s[8];
            #pragma unroll
            for (int jj = 0; jj < 8; jj++) {
                const float4* kr = (const float4*)Ks[jc + jj];
                float a0 = 0.f, a1 = 0.f, a2 = 0.f, a3 = 0.f;
                #pragma unroll
                for (int d4 = 0; d4 < 16; d4 += 4) {
                    float4 k0 = kr[d4 + 0], k1 = kr[d4 + 1];
                    float4 k2 = kr[d4 + 2], k3 = kr[d4 + 3];
                    a0 += q[4*d4 +  0]*k0.x + q[4*d4 +  1]*k0.y
                        + q[4*d4 +  2]*k0.z + q[4*d4 +  3]*k0.w;
                    a1 += q[4*d4 +  4]*k1.x + q[4*d4 +  5]*k1.y
                        + q[4*d4 +  6]*k1.z + q[4*d4 +  7]*k1.w;
                    a2 += q[4*d4 +  8]*k2.x + q[4*d4 +  9]*k2.y
                        + q[4*d4 + 10]*k2.z + q[4*d4 + 11]*k2.w;
                    a3 += q[4*d4 + 12]*k3.x + q[4*d4 + 13]*k3.y
                        + q[4*d4 + 14]*k3.z + q[4*d4 + 15]*k3.w;
                }
                s[jj] = (a0 + a1) + (a2 + a3) + Ms[jc + jj];
            }

            float cmax = s[0];
            #pragma unroll
            for (int jj = 1; jj < 8; jj++) cmax = fmaxf(cmax, s[jj]);
            float mnew = fmaxf(mrun, cmax);
            float corr = __expf(mrun - mnew);
            mrun = mnew;
            lrun *= corr;
            #pragma unroll
            for (int d = 0; d < 64; d++) o[d] *= corr;

            #pragma unroll
            for (int jj = 0; jj < 8; jj++) {
                float p = __expf(s[jj] - mnew);
                lrun += p;
                const float4* vr = (const float4*)Vs[jc + jj];
                #pragma unroll
                for (int d4 = 0; d4 < 16; d4++) {
                    float4 vv = vr[d4];
                    o[4*d4 + 0] += p * vv.x;
                    o[4*d4 + 1] += p * vv.y;
                    o[4*d4 + 2] += p * vv.z;
                    o[4*d4 + 3] += p * vv.w;
                }
            }
        }
    }

    const float inv = 1.0f / lrun;
    float* op = out + ((size_t)b * SS + qrow) * HID + h * HD;
    #pragma unroll
    for (int i = 0; i < 16; i++) {
        float4 t;
        t.x = o[4*i + 0] * inv; t.y = o[4*i + 1] * inv;
        t.z = o[4*i + 2] * inv; t.w = o[4*i + 3] * inv;
        ((float4*)op)[i] = t;
    }
}

// ---------------------------------------------------------------------------
extern "C" void kernel_launch(void* const* d_in, const int* in_sizes, int n_in,
                              void* d_out, int out_size)
{
    const float* X    = (const float*)d_in[0];
    const float* mask = (const float*)d_in[1];
    const float* Wq   = (const float*)d_in[2];
    const float* bq   = (const float*)d_in[3];
    const float* Wk   = (const float*)d_in[4];
    const float* bk   = (const float*)d_in[5];
    const float* Wv   = (const float*)d_in[6];
    const float* bv   = (const float*)d_in[7];
    float* out = (float*)d_out;

    cudaFuncSetAttribute(qkv_gemm_mma,
                         cudaFuncAttributeMaxDynamicSharedMemorySize, SMEM_GEMM);

    cvt_kernel<<<8192, 256>>>(X,  0, 0, BB * SS * HID);
    cvt_kernel<<<1024, 256>>>(Wq, 1, 0, HID * HID);
    cvt_kernel<<<1024, 256>>>(Wk, 1, 1, HID * HID);
    cvt_kernel<<<1024, 256>>>(Wv, 1, 2, HID * HID);

    dim3 g1(64, 8, 3);                 // M/128, N/128, {Q,K,V}
    qkv_gemm_mma<<<g1, 256, SMEM_GEMM>>>(bq, bk, bv);

    dim3 g2(8, 128);                   // S/128, B*NH
    flash_kernel<<<g2, 128>>>(mask, out);
}

// round 9
// speedup vs baseline: 1.4123x; 1.0011x over previous
#include <cuda_runtime.h>
#include <cuda_bf16.h>
#include <cstdint>

#define BB   8
#define SS   1024
#define HID  1024
#define NH   16
#define HD   64

// ---------------------------------------------------------------------------
// Device scratch (allocation-free rule): Q/K/V fp32 in [b,h,s,d], plus
// bf16 hi/lo splits of X and the three weight matrices.
// ---------------------------------------------------------------------------
__device__ float g_Q[BB * NH * SS * HD];
__device__ float g_K[BB * NH * SS * HD];
__device__ float g_V[BB * NH * SS * HD];
__device__ __nv_bfloat16 g_Xh[BB * SS * HID];
__device__ __nv_bfloat16 g_Xl[BB * SS * HID];
__device__ __nv_bfloat16 g_Wh[3 * HID * HID];
__device__ __nv_bfloat16 g_Wl[3 * HID * HID];

// ---------------------------------------------------------------------------
// PTX helpers available on plain sm_100 target (sm_80+ features only).
// ---------------------------------------------------------------------------
__device__ __forceinline__ uint32_t smem_u32(const void* p) {
    uint32_t a;
    asm("{ .reg .u64 t; cvta.to.shared.u64 t, %1; cvt.u32.u64 %0, t; }"
        : "=r"(a) : "l"(p));
    return a;
}
__device__ __forceinline__ void cp16(uint32_t s, const void* g) {
    asm volatile("cp.async.cg.shared.global [%0], [%1], 16;" :: "r"(s), "l"(g));
}
#define CP_COMMIT() asm volatile("cp.async.commit_group;" ::: "memory")
#define CP_WAIT(n)  asm volatile("cp.async.wait_group %0;" :: "n"(n) : "memory")

__device__ __forceinline__ void ldsm_x4(uint32_t* r, uint32_t a) {
    asm volatile("ldmatrix.sync.aligned.m8n8.x4.shared.b16 {%0,%1,%2,%3}, [%4];"
                 : "=r"(r[0]), "=r"(r[1]), "=r"(r[2]), "=r"(r[3]) : "r"(a));
}
// NON-trans x2: for B stored [n][k] (k contiguous) this directly yields the
// mma row.col B fragment (thread t: n = t/4, k = 2*(t%4)+j).
__device__ __forceinline__ void ldsm_x2(uint32_t* r, uint32_t a) {
    asm volatile("ldmatrix.sync.aligned.m8n8.x2.shared.b16 {%0,%1}, [%2];"
                 : "=r"(r[0]), "=r"(r[1]) : "r"(a));
}
__device__ __forceinline__ void mma_bf16(float* d, const uint32_t* a,
                                         const uint32_t* b) {
    asm volatile("mma.sync.aligned.m16n8k16.row.col.f32.bf16.bf16.f32 "
                 "{%0,%1,%2,%3}, {%4,%5,%6,%7}, {%8,%9}, {%0,%1,%2,%3};"
                 : "+f"(d[0]), "+f"(d[1]), "+f"(d[2]), "+f"(d[3])
                 : "r"(a[0]), "r"(a[1]), "r"(a[2]), "r"(a[3]),
                   "r"(b[0]), "r"(b[1]));
}

// ---------------------------------------------------------------------------
// Convert fp32 -> bf16 hi + bf16 lo (residual).  which: 0 = X, 1 = W[z]
// ---------------------------------------------------------------------------
__global__ __launch_bounds__(256) void cvt_kernel(const float* __restrict__ src,
                                                  int which, int z, int n)
{
    int i = (blockIdx.x * 256 + threadIdx.x) * 4;
    if (i >= n) return;
    __nv_bfloat16* hi = (which == 0) ? g_Xh : (g_Wh + (size_t)z * HID * HID);
    __nv_bfloat16* lo = (which == 0) ? g_Xl : (g_Wl + (size_t)z * HID * HID);
    float4 v = *(const float4*)(src + i);
    __nv_bfloat16 h0 = __float2bfloat16(v.x), h1 = __float2bfloat16(v.y);
    __nv_bfloat16 h2 = __float2bfloat16(v.z), h3 = __float2bfloat16(v.w);
    __nv_bfloat16 l0 = __float2bfloat16(v.x - __bfloat162float(h0));
    __nv_bfloat16 l1 = __float2bfloat16(v.y - __bfloat162float(h1));
    __nv_bfloat16 l2 = __float2bfloat16(v.z - __bfloat162float(h2));
    __nv_bfloat16 l3 = __float2bfloat16(v.w - __bfloat162float(h3));
    ((__nv_bfloat162*)(hi + i))[0] = __nv_bfloat162(h0, h1);
    ((__nv_bfloat162*)(hi + i))[1] = __nv_bfloat162(h2, h3);
    ((__nv_bfloat162*)(lo + i))[0] = __nv_bfloat162(l0, l1);
    ((__nv_bfloat162*)(lo + i))[1] = __nv_bfloat162(l2, l3);
}

// ---------------------------------------------------------------------------
// mma.sync QKV GEMM: C[8192,1024] = X·W^T + bias, z selects {Q,K,V}.
// 128x128 CTA tile, 8 warps (2x4), warp tile 64x32, BK=32, cp.async
// double-buffered, hi/lo bf16 split (3 mma products per tile).
// SMEM per stage: 4 matrices x 128 rows x stride 40 bf16 = 40960 B.
// ---------------------------------------------------------------------------
#define STRIDE   40                       // bf16 elements per smem row (pad 8)
#define MAT_SZ   (128 * STRIDE * 2)       // 10240 bytes
#define STAGE_SZ (4 * MAT_SZ)             // 40960 bytes
#define SMEM_GEMM (2 * STAGE_SZ)          // 81920 bytes
#define NSTAGES  (HID / 32)               // 32

__global__ __launch_bounds__(256) void qkv_gemm_mma(
    const float* __restrict__ bq, const float* __restrict__ bk,
    const float* __restrict__ bv)
{
    extern __shared__ char smem[];
    const uint32_t sb = smem_u32(smem);
    const int tid  = threadIdx.x;
    const int wid  = tid >> 5;
    const int lane = tid & 31;
    const int wm   = wid >> 2;            // 0..1  (m offset /64)
    const int wn   = wid & 3;             // 0..3  (n offset /32)

    const int z  = blockIdx.z;
    const int m0 = blockIdx.x * 128;
    const int n0 = blockIdx.y * 128;
    const float* __restrict__ bias = (z == 0) ? bq : (z == 1) ? bk : bv;
    float* __restrict__ dst        = (z == 0) ? g_Q : (z == 1) ? g_K : g_V;
    const float scale = (z == 0) ? 0.125f : 1.0f;
    const __nv_bfloat16* __restrict__ gA_h = g_Xh + (size_t)m0 * HID;
    const __nv_bfloat16* __restrict__ gA_l = g_Xl + (size_t)m0 * HID;
    const __nv_bfloat16* __restrict__ gB_h = g_Wh + (size_t)z * HID * HID + (size_t)n0 * HID;
    const __nv_bfloat16* __restrict__ gB_l = g_Wl + (size_t)z * HID * HID + (size_t)n0 * HID;

    float acc[4][4][4];
    #pragma unroll
    for (int mi = 0; mi < 4; mi++)
        #pragma unroll
        for (int ni = 0; ni < 4; ni++)
            #pragma unroll
            for (int e = 0; e < 4; e++) acc[mi][ni][e] = 0.0f;

    // per-lane ldmatrix address components
    const int aRow = lane & 15;             // row within 16-row tile
    const int aCol = (lane >> 4) * 8;       // k half
    const int bRow = lane & 7;              // n row within 8
    const int bCol = ((lane >> 3) & 1) * 8; // k half (lanes 0-15 used)

    // stage loader: 512 16B-chunks per matrix, 2 per thread per matrix
    auto load_stage = [&](int c, int st) {
        const __nv_bfloat16* gb[4] = { gA_h + c * 32, gA_l + c * 32,
                                       gB_h + c * 32, gB_l + c * 32 };
        const uint32_t sbase = sb + st * STAGE_SZ;
        #pragma unroll
        for (int j = 0; j < 2; j++) {
            const int t   = tid + j * 256;
            const int row = t >> 2;
            const int cb  = t & 3;
            const uint32_t soff = (uint32_t)(row * STRIDE + cb * 8) * 2;
            const size_t  goff  = (size_t)row * HID + cb * 8;
            #pragma unroll
            for (int mt = 0; mt < 4; mt++)
                cp16(sbase + mt * MAT_SZ + soff, gb[mt] + goff);
        }
    };

    load_stage(0, 0);
    CP_COMMIT();

    for (int c = 0; c < NSTAGES; c++) {
        const int st = c & 1;
        if (c + 1 < NSTAGES) {
            load_stage(c + 1, st ^ 1);
            CP_COMMIT();
            CP_WAIT(1);
        } else {
            CP_WAIT(0);
        }
        __syncthreads();

        const uint32_t sbase = sb + st * STAGE_SZ;
        #pragma unroll
        for (int ks = 0; ks < 2; ks++) {
            uint32_t ah[4][4], al[4][4], bh[4][2], bl[4][2];
            #pragma unroll
            for (int mi = 0; mi < 4; mi++) {
                const uint32_t ro = (uint32_t)((wm * 64 + mi * 16 + aRow) * STRIDE
                                               + ks * 16 + aCol) * 2;
                ldsm_x4(ah[mi], sbase + 0 * MAT_SZ + ro);
                ldsm_x4(al[mi], sbase + 1 * MAT_SZ + ro);
            }
            #pragma unroll
            for (int ni = 0; ni < 4; ni++) {
                const uint32_t ro = (uint32_t)((wn * 32 + ni * 8 + bRow) * STRIDE
                                               + ks * 16 + bCol) * 2;
                ldsm_x2(bh[ni], sbase + 2 * MAT_SZ + ro);
                ldsm_x2(bl[ni], sbase + 3 * MAT_SZ + ro);
            }
            #pragma unroll
            for (int mi = 0; mi < 4; mi++)
                #pragma unroll
                for (int ni = 0; ni < 4; ni++) {
                    mma_bf16(acc[mi][ni], ah[mi], bh[ni]);
                    mma_bf16(acc[mi][ni], ah[mi], bl[ni]);
                    mma_bf16(acc[mi][ni], al[mi], bh[ni]);
                }
        }
        __syncthreads();
    }

    // Epilogue: d0,d1 -> (row, col+0/1); d2,d3 -> (row+8, col+0/1)
    const int r0 = lane >> 2;
    const int cp = (lane & 3) * 2;
    #pragma unroll
    for (int mi = 0; mi < 4; mi++) {
        #pragma unroll
        for (int ni = 0; ni < 4; ni++) {
            const int n  = n0 + wn * 32 + ni * 8 + cp;
            const int h  = n >> 6;
            const int d  = n & 63;
            const float b0 = bias[n], b1 = bias[n + 1];
            #pragma unroll
            for (int half = 0; half < 2; half++) {
                const int m    = m0 + wm * 64 + mi * 16 + r0 + half * 8;
                const int bidx = m >> 10;
                const int srow = m & 1023;
                float2 v;
                v.x = (acc[mi][ni][half * 2 + 0] + b0) * scale;
                v.y = (acc[mi][ni][half * 2 + 1] + b1) * scale;
                *(float2*)(dst + (((size_t)(bidx * NH + h)) * SS + srow) * HD + d) = v;
            }
        }
    }
}

// ---------------------------------------------------------------------------
// Kernel 2: flash attention (online softmax), fp32 — unchanged (proven).
// ---------------------------------------------------------------------------
__global__ __launch_bounds__(128) void flash_kernel(
    const float* __restrict__ mask, float* __restrict__ out)
{
    __shared__ float Ks[64][64];
    __shared__ float Vs[64][64];
    __shared__ float Ms[64];

    const int tid  = threadIdx.x;
    const int bh   = blockIdx.y;
    const int b    = bh >> 4;
    const int h    = bh & 15;
    const int qrow = blockIdx.x * 128 + tid;

    const float* __restrict__ qp = g_Q + ((size_t)bh * SS + qrow) * HD;
    const float* __restrict__ kb = g_K + (size_t)bh * SS * HD;
    const float* __restrict__ vb = g_V + (size_t)bh * SS * HD;
    const float* __restrict__ mp = mask + (size_t)b * SS;

    float q[64];
    #pragma unroll
    for (int i = 0; i < 16; i++) {
        float4 t = ((const float4*)qp)[i];
        q[4*i + 0] = t.x; q[4*i + 1] = t.y;
        q[4*i + 2] = t.z; q[4*i + 3] = t.w;
    }

    float o[64];
    #pragma unroll
    for (int d = 0; d < 64; d++) o[d] = 0.0f;
    float mrun = -1e30f, lrun = 0.0f;

    for (int kt = 0; kt < SS; kt += 64) {
        __syncthreads();
        #pragma unroll
        for (int i = 0; i < 8; i++) {
            int idx = i * 512 + tid * 4;
            *(float4*)&Ks[0][idx] = *(const float4*)(kb + (size_t)kt * HD + idx);
            *(float4*)&Vs[0][idx] = *(const float4*)(vb + (size_t)kt * HD + idx);
        }
        if (tid < 64) Ms[tid] = mp[kt + tid];
        __syncthreads();

        for (int jc = 0; jc < 64; jc += 8) {
            float s[8];
            #pragma unroll
            for (int jj = 0; jj < 8; jj++) {
                const float4* kr = (const float4*)Ks[jc + jj];
                float a0 = 0.f, a1 = 0.f, a2 = 0.f, a3 = 0.f;
                #pragma unroll
                for (int d4 = 0; d4 < 16; d4 += 4) {
                    float4 k0 = kr[d4 + 0], k1 = kr[d4 + 1];
                    float4 k2 = kr[d4 + 2], k3 = kr[d4 + 3];
                    a0 += q[4*d4 +  0]*k0.x + q[4*d4 +  1]*k0.y
                        + q[4*d4 +  2]*k0.z + q[4*d4 +  3]*k0.w;
                    a1 += q[4*d4 +  4]*k1.x + q[4*d4 +  5]*k1.y
                        + q[4*d4 +  6]*k1.z + q[4*d4 +  7]*k1.w;
                    a2 += q[4*d4 +  8]*k2.x + q[4*d4 +  9]*k2.y
                        + q[4*d4 + 10]*k2.z + q[4*d4 + 11]*k2.w;
                    a3 += q[4*d4 + 12]*k3.x + q[4*d4 + 13]*k3.y
                        + q[4*d4 + 14]*k3.z + q[4*d4 + 15]*k3.w;
                }
                s[jj] = (a0 + a1) + (a2 + a3) + Ms[jc + jj];
            }

            float cmax = s[0];
            #pragma unroll
            for (int jj = 1; jj < 8; jj++) cmax = fmaxf(cmax, s[jj]);
            float mnew = fmaxf(mrun, cmax);
            float corr = __expf(mrun - mnew);
            mrun = mnew;
            lrun *= corr;
            #pragma unroll
            for (int d = 0; d < 64; d++) o[d] *= corr;

            #pragma unroll
            for (int jj = 0; jj < 8; jj++) {
                float p = __expf(s[jj] - mnew);
                lrun += p;
                const float4* vr = (const float4*)Vs[jc + jj];
                #pragma unroll
                for (int d4 = 0; d4 < 16; d4++) {
                    float4 vv = vr[d4];
                    o[4*d4 + 0] += p * vv.x;
                    o[4*d4 + 1] += p * vv.y;
                    o[4*d4 + 2] += p * vv.z;
                    o[4*d4 + 3] += p * vv.w;
                }
            }
        }
    }

    const float inv = 1.0f / lrun;
    float* op = out + ((size_t)b * SS + qrow) * HID + h * HD;
    #pragma unroll
    for (int i = 0; i < 16; i++) {
        float4 t;
        t.x = o[4*i + 0] * inv; t.y = o[4*i + 1] * inv;
        t.z = o[4*i + 2] * inv; t.w = o[4*i + 3] * inv;
        ((float4*)op)[i] = t;
    }
}

// ---------------------------------------------------------------------------
extern "C" void kernel_launch(void* const* d_in, const int* in_sizes, int n_in,
                              void* d_out, int out_size)
{
    const float* X    = (const float*)d_in[0];
    const float* mask = (const float*)d_in[1];
    const float* Wq   = (const float*)d_in[2];
    const float* bq   = (const float*)d_in[3];
    const float* Wk   = (const float*)d_in[4];
    const float* bk   = (const float*)d_in[5];
    const float* Wv   = (const float*)d_in[6];
    const float* bv   = (const float*)d_in[7];
    float* out = (float*)d_out;

    cudaFuncSetAttribute(qkv_gemm_mma,
                         cudaFuncAttributeMaxDynamicSharedMemorySize, SMEM_GEMM);

    cvt_kernel<<<8192, 256>>>(X,  0, 0, BB * SS * HID);
    cvt_kernel<<<1024, 256>>>(Wq, 1, 0, HID * HID);
    cvt_kernel<<<1024, 256>>>(Wk, 1, 1, HID * HID);
    cvt_kernel<<<1024, 256>>>(Wv, 1, 2, HID * HID);

    dim3 g1(64, 8, 3);                 // M/128, N/128, {Q,K,V}
    qkv_gemm_mma<<<g1, 256, SMEM_GEMM>>>(bq, bk, bv);

    dim3 g2(8, 128);                   // S/128, B*NH
    flash_kernel<<<g2, 128>>>(mask, out);
}